// round 16
// baseline (speedup 1.0000x reference)
#include <cuda_runtime.h>
#include <cstddef>

#define C_DIM 64
#define K_DIM 64
#define P_DIM (256 * 256)        // H*W = 65536
#define RED_BLOCKS 256           // reduction blocks (256 pixels each)
#define CHUNKS_PER_REP 2048      // 8 KB chunks (measured optimum granularity)
#define REPS_PER_BLOCK 4         // read chunk once, store to 4 replicas
#define KGROUPS (K_DIM / REPS_PER_BLOCK)            // 16 replica groups
#define COPY_BLOCKS (KGROUPS * CHUNKS_PER_REP)      // 32768
#define N4_PER_REP (C_DIM * P_DIM / 4)              // 1,048,576 float4 per replica
#define F4_PER_CHUNK (N4_PER_REP / CHUNKS_PER_REP)  // 512 float4 = 8KB

// Global accumulators. Zero-initialized at load; the means kernel re-zeroes
// them at the end of every launch, so every graph replay starts from zero.
__device__ float g_sums[K_DIM * C_DIM];   // 16 KB
__device__ float g_counts[K_DIM];

// ---------------------------------------------------------------------------
// Fused kernel: blocks [0,256) reduce, rest stream the 1 GiB broadcast.
// Copy path: read one 8 KB chunk ONCE (2x LDG.128), store to 4 replicas
// (8x STG.128 __stcs). Cuts redundant L2 read traffic 1 GiB -> 268 MB,
// leaving the LTS to spend its bandwidth on the mandatory write stream.
// ---------------------------------------------------------------------------
__global__ __launch_bounds__(256) void fused_kernel(
    const float* __restrict__ x, const float* __restrict__ oh,
    float4* __restrict__ out4)
{
    int bid = blockIdx.x;
    int tid = threadIdx.x;

    if (bid < RED_BLOCKS) {
        // ---- reduction path: 256 pixels per block ----
        __shared__ float ssum[K_DIM][C_DIM + 1];  // padded rows vs bank conflicts
        __shared__ float scnt[K_DIM];

        for (int i = tid; i < K_DIM * (C_DIM + 1); i += 256)
            (&ssum[0][0])[i] = 0.0f;
        if (tid < K_DIM) scnt[tid] = 0.0f;
        __syncthreads();

        int p = bid * 256 + tid;

        // Recover the one-hot label (coalesced scan over K).
        int label = 0;
        #pragma unroll 8
        for (int k = 0; k < K_DIM; k++) {
            if (__ldg(&oh[(size_t)k * P_DIM + p]) != 0.0f) label = k;
        }
        atomicAdd(&scnt[label], 1.0f);

        #pragma unroll 8
        for (int c = 0; c < C_DIM; c++) {
            atomicAdd(&ssum[label][c], __ldg(&x[(size_t)c * P_DIM + p]));
        }
        __syncthreads();

        // Flush block partials via global atomics (4096 spread addresses,
        // hidden under the DRAM-bound copy).
        for (int i = tid; i < K_DIM * C_DIM; i += 256) {
            float v = ssum[i >> 6][i & 63];
            if (v != 0.0f) atomicAdd(&g_sums[i], v);
        }
        if (tid < K_DIM) {
            float v = scnt[tid];
            if (v != 0.0f) atomicAdd(&g_counts[tid], v);
        }
    } else {
        // ---- broadcast path: one 8 KB chunk -> 4 replicas ----
        int b  = bid - RED_BLOCKS;
        int kg = b >> 11;                    // replica group (2048 chunks/rep)
        int cb = b & (CHUNKS_PER_REP - 1);

        const float4* src = (const float4*)x + (size_t)cb * F4_PER_CHUNK;
        float4 v0 = __ldg(src + tid);
        float4 v1 = __ldg(src + 256 + tid);

        float4* dst = out4 + (size_t)(kg * REPS_PER_BLOCK) * N4_PER_REP
                           + (size_t)cb * F4_PER_CHUNK;
        #pragma unroll
        for (int r = 0; r < REPS_PER_BLOCK; r++) {
            __stcs(dst + tid,       v0);
            __stcs(dst + 256 + tid, v1);
            dst += N4_PER_REP;
        }
    }
}

// ---------------------------------------------------------------------------
// Means: one thread per (k,c); 16 KB of reads, one divide. Self-resets the
// accumulators for the next graph replay (block-exclusive k ranges).
// ---------------------------------------------------------------------------
__global__ __launch_bounds__(256) void means_kernel(float* __restrict__ out_means)
{
    int i = blockIdx.x * 256 + threadIdx.x;   // 0..4095
    int k = i >> 6;

    float s   = g_sums[i];
    float cnt = g_counts[k];

    __syncthreads();   // all reads of this block's g_counts range done

    g_sums[i] = 0.0f;
    if ((i & 63) == 0) g_counts[k] = 0.0f;   // k exclusive to this block

    float denom = cnt + (cnt == 0.0f ? 1.0f : 0.0f);
    out_means[i] = s / denom;
}

// ---------------------------------------------------------------------------
extern "C" void kernel_launch(void* const* d_in, const int* in_sizes, int n_in,
                              void* d_out, int out_size)
{
    const float* x  = (const float*)d_in[0];   // [1, 64, 256, 256]
    const float* oh = (const float*)d_in[1];   // [1, 64, 256, 256] one-hot
    float* out = (float*)d_out;

    // Output layout: input_r (K*C*H*W floats) then regional_means (K*C).
    float* out_means = out + (size_t)out_size - (size_t)(K_DIM * C_DIM);

    fused_kernel<<<RED_BLOCKS + COPY_BLOCKS, 256>>>(x, oh, (float4*)out);
    means_kernel<<<(K_DIM * C_DIM) / 256, 256>>>(out_means);
}

// round 17
// speedup vs baseline: 1.0894x; 1.0894x over previous
#include <cuda_runtime.h>
#include <cstddef>

#define C_DIM 64
#define K_DIM 64
#define P_DIM (256 * 256)        // H*W = 65536
#define RED_BLOCKS 256           // reduction blocks (256 pixels each)
#define CHUNKS_PER_REP 2048      // 8 KB chunks — measured optimum
#define COPY_BLOCKS (K_DIM * CHUNKS_PER_REP)        // 131072
#define N4_PER_REP (C_DIM * P_DIM / 4)              // 1,048,576 float4 per replica
#define F4_PER_CHUNK (N4_PER_REP / CHUNKS_PER_REP)  // 512 float4 = 8KB

// Global accumulators. Zero-initialized at load; the means kernel re-zeroes
// them at the end of every launch, so every graph replay starts from zero.
__device__ float g_sums[K_DIM * C_DIM];   // 16 KB
__device__ float g_counts[K_DIM];

// ---------------------------------------------------------------------------
// Fused kernel (champion data path, byte-identical): blocks [0,256) reduce,
// rest stream the 1 GiB broadcast at the DRAM write ceiling. Each block
// triggers PDL completion after its work — reduction blocks AFTER the atomic
// flush, so the trigger set implies all partials are globally visible.
// ---------------------------------------------------------------------------
__global__ __launch_bounds__(256) void fused_kernel(
    const float* __restrict__ x, const float* __restrict__ oh,
    float4* __restrict__ out4)
{
    int bid = blockIdx.x;
    int tid = threadIdx.x;

    if (bid < RED_BLOCKS) {
        // ---- reduction path: 256 pixels per block ----
        __shared__ float ssum[K_DIM][C_DIM + 1];  // padded rows vs bank conflicts
        __shared__ float scnt[K_DIM];

        for (int i = tid; i < K_DIM * (C_DIM + 1); i += 256)
            (&ssum[0][0])[i] = 0.0f;
        if (tid < K_DIM) scnt[tid] = 0.0f;
        __syncthreads();

        int p = bid * 256 + tid;

        // Recover the one-hot label (coalesced scan over K).
        int label = 0;
        #pragma unroll 8
        for (int k = 0; k < K_DIM; k++) {
            if (__ldg(&oh[(size_t)k * P_DIM + p]) != 0.0f) label = k;
        }
        atomicAdd(&scnt[label], 1.0f);

        #pragma unroll 8
        for (int c = 0; c < C_DIM; c++) {
            atomicAdd(&ssum[label][c], __ldg(&x[(size_t)c * P_DIM + p]));
        }
        __syncthreads();

        // Flush block partials via global atomics (4096 spread addresses,
        // hidden under the DRAM-bound copy).
        for (int i = tid; i < K_DIM * C_DIM; i += 256) {
            float v = ssum[i >> 6][i & 63];
            if (v != 0.0f) atomicAdd(&g_sums[i], v);
        }
        if (tid < K_DIM) {
            float v = scnt[tid];
            if (v != 0.0f) atomicAdd(&g_counts[tid], v);
        }
        __syncthreads();
        cudaTriggerProgrammaticLaunchCompletion();
    } else {
        // ---- broadcast path: one 8 KB chunk of one replica ----
        int b  = bid - RED_BLOCKS;
        int k  = b >> 11;                    // replica index (2048 chunks/rep)
        int cb = b & (CHUNKS_PER_REP - 1);

        const float4* src = (const float4*)x + (size_t)cb * F4_PER_CHUNK;
        float4* dst = out4 + (size_t)k * N4_PER_REP + (size_t)cb * F4_PER_CHUNK;

        float4 v0 = __ldg(src + tid);
        float4 v1 = __ldg(src + 256 + tid);
        __stcs(dst + tid,       v0);
        __stcs(dst + 256 + tid, v1);
        cudaTriggerProgrammaticLaunchCompletion();
    }
}

// ---------------------------------------------------------------------------
// Means: PDL consumer. Grid-sync waits until all fused blocks have triggered
// (=> all partials visible), overlapping this kernel's launch/prolog with the
// fused kernel's tail. Then: one thread per (k,c), divide, self-reset.
// ---------------------------------------------------------------------------
__global__ __launch_bounds__(256) void means_kernel(float* __restrict__ out_means)
{
    cudaGridDependencySynchronize();

    int i = blockIdx.x * 256 + threadIdx.x;   // 0..4095
    int k = i >> 6;

    float s   = g_sums[i];
    float cnt = g_counts[k];

    __syncthreads();   // all reads of this block's g_counts range done

    g_sums[i] = 0.0f;
    if ((i & 63) == 0) g_counts[k] = 0.0f;   // k exclusive to this block

    float denom = cnt + (cnt == 0.0f ? 1.0f : 0.0f);
    out_means[i] = s / denom;
}

// ---------------------------------------------------------------------------
extern "C" void kernel_launch(void* const* d_in, const int* in_sizes, int n_in,
                              void* d_out, int out_size)
{
    const float* x  = (const float*)d_in[0];   // [1, 64, 256, 256]
    const float* oh = (const float*)d_in[1];   // [1, 64, 256, 256] one-hot
    float* out = (float*)d_out;

    // Output layout: input_r (K*C*H*W floats) then regional_means (K*C).
    float* out_means = out + (size_t)out_size - (size_t)(K_DIM * C_DIM);

    fused_kernel<<<RED_BLOCKS + COPY_BLOCKS, 256>>>(x, oh, (float4*)out);

    // Means via PDL: allowed to launch before fused_kernel fully completes;
    // its cudaGridDependencySynchronize() enforces the data dependency.
    cudaLaunchConfig_t cfg = {};
    cfg.gridDim  = dim3((K_DIM * C_DIM) / 256);
    cfg.blockDim = dim3(256);
    cudaLaunchAttribute attrs[1];
    attrs[0].id = cudaLaunchAttributeProgrammaticStreamSerialization;
    attrs[0].val.programmaticStreamSerializationAllowed = 1;
    cfg.attrs = attrs;
    cfg.numAttrs = 1;
    cudaLaunchKernelEx(&cfg, means_kernel, out_means);
}